// round 13
// baseline (speedup 1.0000x reference)
#include <cuda_runtime.h>

// Fused Bayer demosaic, rolling vertical stencil (R8 structure).
// Quadrant -> (R,G,B) stencil map:
//   q0 (i even, j even): (diag, plus, center)
//   q1 (i even, j odd ): (vavg, center, havg)
//   q2 (i odd , j even): (havg, center, vavg)
//   q3 (i odd , j odd ): (center, plus, diag)
//
// R10: RROWS=4 + __launch_bounds__(256,8) to cap regs (~32) and keep
// 8 blocks/SM resident -> smoother waves + higher occupancy, while
// retaining R8's minimal load count (1 vector + 2 scalars per row).

#define RROWS 4

__device__ __forceinline__ void load_row6(const float* __restrict__ r,
                                          int j0, int W, bool fast,
                                          float v[6]) {
    if (fast) {
        float4 m = *reinterpret_cast<const float4*>(r + j0);
        v[0] = __ldg(r + j0 - 1);
        v[1] = m.x; v[2] = m.y; v[3] = m.z; v[4] = m.w;
        v[5] = __ldg(r + j0 + 4);
    } else {
#pragma unroll
        for (int k = 0; k < 6; ++k) {
            int c = j0 + k - 1;
            c = (c < 0) ? -c : c;                 // reflect: -1 -> 1
            c = (c >= W) ? (2 * W - 2 - c) : c;   // reflect: W -> W-2
            v[k] = __ldg(r + c);
        }
    }
}

__global__ __launch_bounds__(256, 8) void bayer_demosaic_kernel(
    const float* __restrict__ x, float* __restrict__ y, int H, int W) {
    const int j0 = blockIdx.x * 1024 + threadIdx.x * 4;
    const int i0 = blockIdx.y * RROWS;
    const int n  = blockIdx.z;

    const size_t plane = (size_t)H * W;
    const float* xp = x + (size_t)n * plane;
    float* yp = y + (size_t)n * 3 * plane;

    const bool fast = (j0 > 0) && (j0 + 4 < W);

    float a[6], b[6], c[6];
    {
        const int im1 = (i0 == 0) ? 1 : i0 - 1;     // reflect row -1 -> 1
        load_row6(xp + (size_t)im1 * W,      j0, W, fast, a);
        load_row6(xp + (size_t)i0 * W,       j0, W, fast, b);
        load_row6(xp + (size_t)(i0 + 1) * W, j0, W, fast, c);  // i0+1 <= H-3 < H
    }

#pragma unroll
    for (int t = 0; t < RROWS; ++t) {
        const int i = i0 + t;

        // Preload row i+2 (reflected at the bottom edge) BEFORE computing
        // row i, so the DRAM miss overlaps this row's math + stores.
        float nx[6];
        {
            int rn = i + 2;
            rn = (rn >= H) ? 2 * H - 2 - rn : rn;   // reflect H -> H-2
            load_row6(xp + (size_t)rn * W, j0, W, fast, nx);
        }

        float R[4], G[4], B[4];
#pragma unroll
        for (int s = 0; s < 4; ++s) {
            const float center = b[s + 1];
            const float plus   = 0.25f * ((a[s + 1] + c[s + 1]) + (b[s] + b[s + 2]));
            const float diag   = 0.25f * ((a[s] + a[s + 2]) + (c[s] + c[s + 2]));
            const float havg   = 0.5f  * (b[s] + b[s + 2]);
            const float vavg   = 0.5f  * (a[s + 1] + c[s + 1]);
            // i0 multiple of 4, j0 multiple of 4 -> both parities compile-time
            if ((t & 1) == 0) {
                if ((s & 1) == 0) { R[s] = diag;   G[s] = plus;   B[s] = center; }  // q0
                else              { R[s] = vavg;   G[s] = center; B[s] = havg;   }  // q1
            } else {
                if ((s & 1) == 0) { R[s] = havg;   G[s] = center; B[s] = vavg;   }  // q2
                else              { R[s] = center; G[s] = plus;   B[s] = diag;   }  // q3
            }
        }

        float* yn = yp + (size_t)i * W + j0;
        *reinterpret_cast<float4*>(yn)             = make_float4(R[0], R[1], R[2], R[3]);
        *reinterpret_cast<float4*>(yn + plane)     = make_float4(G[0], G[1], G[2], G[3]);
        *reinterpret_cast<float4*>(yn + 2 * plane) = make_float4(B[0], B[1], B[2], B[3]);

        // rotate rows (register renaming after full unroll)
#pragma unroll
        for (int k = 0; k < 6; ++k) { a[k] = b[k]; b[k] = c[k]; c[k] = nx[k]; }
    }
}

extern "C" void kernel_launch(void* const* d_in, const int* in_sizes, int n_in,
                              void* d_out, int out_size) {
    const float* x = (const float*)d_in[0];
    float* y = (float*)d_out;

    const int H = 4096, W = 4096;
    const int N = in_sizes[0] / (H * W);  // = 2

    dim3 block(256, 1, 1);
    dim3 grid(W / 1024, H / RROWS, N);
    bayer_demosaic_kernel<<<grid, block>>>(x, y, H, W);
}

// round 14
// speedup vs baseline: 1.1763x; 1.1763x over previous
#include <cuda_runtime.h>

// Fused Bayer demosaic (converged optimum = R1).
//   y[n,c,i,j] = one of {center, plus-avg, diag-avg, h-avg, v-avg} of the
//   reflect-padded 3x3 neighborhood of x[n,0,i,j], chosen by (c, i&1, j&1).
//
// Quadrant -> (R,G,B) stencil map (decoded from the constant `sel` input):
//   q0 (i even, j even): (diag, plus, center)
//   q1 (i even, j odd ): (vavg, center, havg)
//   q2 (i odd , j even): (havg, center, vavg)
//   q3 (i odd , j odd ): (center, plus, diag)
//
// HBM-bound at the read/write turnaround wall (~6.5 TB/s useful on the
// 134 MB read + 403 MB write stream). 4 px/thread, 9 independent loads
// per thread issued up front, no smem, no shuffles, 32 regs, occ ~86%.
// Alternatives measured and rejected: __stcs (neutral), 8px/thread
// (-24%), warp-shuffle halos (-10%), smem staging (-12%), rolling
// vertical stencil (equal kernel time, worse wall).

__device__ __forceinline__ void load_row6(const float* __restrict__ r,
                                          int j0, int W, bool fast,
                                          float v[6]) {
    if (fast) {
        float4 m = *reinterpret_cast<const float4*>(r + j0);
        v[0] = __ldg(r + j0 - 1);
        v[1] = m.x; v[2] = m.y; v[3] = m.z; v[4] = m.w;
        v[5] = __ldg(r + j0 + 4);
    } else {
#pragma unroll
        for (int k = 0; k < 6; ++k) {
            int c = j0 + k - 1;
            c = (c < 0) ? -c : c;                 // reflect: -1 -> 1
            c = (c >= W) ? (2 * W - 2 - c) : c;   // reflect: W -> W-2
            v[k] = __ldg(r + c);
        }
    }
}

__global__ __launch_bounds__(256) void bayer_demosaic_kernel(
    const float* __restrict__ x, float* __restrict__ y, int H, int W) {
    const int j0 = (blockIdx.x * blockDim.x + threadIdx.x) * 4;
    const int i  = blockIdx.y;
    const int n  = blockIdx.z;
    if (j0 >= W) return;

    const size_t plane = (size_t)H * W;
    const float* xp = x + (size_t)n * plane;

    const int im1 = (i == 0)     ? 1     : i - 1;   // reflect rows
    const int ip1 = (i == H - 1) ? H - 2 : i + 1;

    const float* ra = xp + (size_t)im1 * W;  // row above
    const float* rb = xp + (size_t)i   * W;  // center row
    const float* rc = xp + (size_t)ip1 * W;  // row below

    const bool fast = (j0 > 0) && (j0 + 4 < W);

    float a[6], b[6], c[6];
    load_row6(ra, j0, W, fast, a);
    load_row6(rb, j0, W, fast, b);
    load_row6(rc, j0, W, fast, c);

    float R[4], G[4], B[4];
    const int ip = i & 1;
#pragma unroll
    for (int t = 0; t < 4; ++t) {
        const float center = b[t + 1];
        const float plus   = 0.25f * ((a[t + 1] + c[t + 1]) + (b[t] + b[t + 2]));
        const float diag   = 0.25f * ((a[t] + a[t + 2]) + (c[t] + c[t + 2]));
        const float havg   = 0.5f  * (b[t] + b[t + 2]);
        const float vavg   = 0.5f  * (a[t + 1] + c[t + 1]);
        const int jp = t & 1;  // j0 is a multiple of 4 -> parity of j == parity of t
        if (ip == 0) {
            if (jp == 0) { R[t] = diag;   G[t] = plus;   B[t] = center; }  // q0
            else         { R[t] = vavg;   G[t] = center; B[t] = havg;   }  // q1
        } else {
            if (jp == 0) { R[t] = havg;   G[t] = center; B[t] = vavg;   }  // q2
            else         { R[t] = center; G[t] = plus;   B[t] = diag;   }  // q3
        }
    }

    float* yn = y + (size_t)n * 3 * plane + (size_t)i * W + j0;
    *reinterpret_cast<float4*>(yn)             = make_float4(R[0], R[1], R[2], R[3]);
    *reinterpret_cast<float4*>(yn + plane)     = make_float4(G[0], G[1], G[2], G[3]);
    *reinterpret_cast<float4*>(yn + 2 * plane) = make_float4(B[0], B[1], B[2], B[3]);
}

extern "C" void kernel_launch(void* const* d_in, const int* in_sizes, int n_in,
                              void* d_out, int out_size) {
    const float* x = (const float*)d_in[0];
    float* y = (float*)d_out;

    const int H = 4096, W = 4096;
    const int N = in_sizes[0] / (H * W);  // = 2

    dim3 block(256, 1, 1);
    dim3 grid((W / 4 + 255) / 256, H, N);
    bayer_demosaic_kernel<<<grid, block>>>(x, y, H, W);
}